// round 6
// baseline (speedup 1.0000x reference)
#include <cuda_runtime.h>
#include <math.h>

// Problem constants
#define NB   64
#define SEQ  512
#define IN   256
#define HID  1024
#define ONN  256

// Kernel config
#define GRID 128          // 4 batch-groups x 32 j-tiles, all co-resident (<=148 SMs)
#define NTH  256
#define BT   16           // batches per CTA (per group)
#define JT   32           // j (hidden) per CTA
#define KW   128          // W_hh k-range per thread (HID / 8 warps)
#define KI   32           // W_ih k-range per thread (IN / 8 warps)
#define GCTA 32           // CTAs per batch-group

// 128 MB scratch for x_proj[t][b][j]
__device__ float g_xp[(size_t)SEQ * NB * HID];
__device__ unsigned g_cnt[4];        // one-shot barrier counters (zero-init at load)
__device__ unsigned g_gen[4];
__device__ unsigned g_cnt_all;
__device__ unsigned g_gen_all;
__device__ unsigned g_flag[4][32];   // per-group scan-step flags (monotonic across replays)

// packed fp32x2 FMA: c += a * b (elementwise on 2 floats)
__device__ __forceinline__ void ffma2(unsigned long long& c, unsigned long long a, unsigned long long b) {
    asm("fma.rn.f32x2 %0, %1, %2, %0;" : "+l"(c) : "l"(a), "l"(b));
}
__device__ __forceinline__ float red2(unsigned long long v) {
    float x, y;
    asm("mov.b64 {%0,%1}, %2;" : "=f"(x), "=f"(y) : "l"(v));
    return x + y;
}

// One-shot arrive-and-wait barrier (atomic counter + generation). Used off the
// hot path only. Pattern == cooperative-groups grid.sync().
__device__ __forceinline__ void sw_barrier(unsigned* cnt, unsigned* gen, unsigned expected) {
    __syncthreads();
    if (threadIdx.x == 0) {
        unsigned g;
        asm volatile("ld.relaxed.gpu.global.u32 %0, [%1];" : "=r"(g) : "l"(gen));
        unsigned arrived;
        asm volatile("atom.acq_rel.gpu.global.add.u32 %0, [%1], %2;"
                     : "=r"(arrived) : "l"(cnt), "r"(1u));
        if (arrived == expected - 1) {
            asm volatile("st.relaxed.gpu.global.u32 [%0], %1;" :: "l"(cnt), "r"(0u));
            asm volatile("st.release.gpu.global.u32 [%0], %1;" :: "l"(gen), "r"(g + 1u));
        } else {
            unsigned cur;
            do {
                asm volatile("ld.acquire.gpu.global.u32 %0, [%1];" : "=r"(cur) : "l"(gen));
            } while (cur == g);
        }
    }
    __syncthreads();
}

__global__ void __launch_bounds__(NTH, 1)
rnn_kernel(const float* __restrict__ x,
           const float* __restrict__ w_ih,
           const float* __restrict__ w_hh,
           const float* __restrict__ bias,
           const float* __restrict__ fc_w,
           const float* __restrict__ fc_b,
           float* __restrict__ out)
{
    extern __shared__ float smem[];
    float* stage    = smem;             // BT*HID floats (64 KB); phase0 ping-pongs 2x32KB inside
    float* partials = smem + BT * HID;  // 2 * 8*512 floats (32 KB; phase0 uses both sets)

    const int tid  = threadIdx.x;
    const int w    = tid >> 5;
    const int lane = tid & 31;
    const int bt = blockIdx.x >> 5;   // 0..3  (batch group)
    const int jt = blockIdx.x & 31;   // 0..31 (j tile within group)
    const int b0 = bt * BT;
    const int j0 = jt * JT;
    const int j  = j0 + lane;         // this lane's output column

    float* hs = out + NB * ONN;       // hidden_states region [SEQ+1][NB][HID]

    // zero hs[0] rows owned by this group (group-local, so group barrier covers it)
    {
        float2* dst = (float2*)(hs + (size_t)b0 * HID);
        dst[jt * NTH + tid] = make_float2(0.f, 0.f);   // 32*256 float2 = 16*1024 floats
    }

    // ---------------- phase 0: x_proj = x @ W_ih^T (parallel over t; 2x unroll,
    //                  stage double-buffered so no trailing sync) ---------------
    {
        const int ki0 = w * KI;
        unsigned long long wih[KI / 2];
        {
            const ulonglong2* wrow = (const ulonglong2*)(w_ih + (size_t)j * IN + ki0);
            #pragma unroll
            for (int i = 0; i < KI / 4; i++) { ulonglong2 v = wrow[i]; wih[2*i] = v.x; wih[2*i+1] = v.y; }
        }
        for (int t = 0; t < SEQ; t += 2) {
            // ping-pong stage buffer: even pairs use [0,8192), odd pairs [8192,16384)
            float* stg = stage + ((t >> 1) & 1) * (2 * BT * IN);

            // stage x[b0..b0+15][t..t+1][:] -> stg[s][b][i]  (2 timesteps)
            for (int idx = tid; idx < 2 * BT * IN / 4; idx += NTH) {
                int s  = idx >> 10;          // timestep within pair (1024 float4 per t)
                int r  = idx & 1023;
                int b  = r >> 6;             // IN/4 = 64
                int i4 = r & 63;
                ((float4*)stg)[idx] =
                    ((const float4*)(x + ((size_t)(b0 + b) * SEQ + t + s) * IN))[i4];
            }
            __syncthreads();   // also orders prev-iter partials reads before this iter's writes
            unsigned long long acc[2][BT];
            #pragma unroll
            for (int s = 0; s < 2; s++)
                #pragma unroll
                for (int b = 0; b < BT; b++) acc[s][b] = 0ull;
            #pragma unroll
            for (int kk = 0; kk < KI / 4; kk++) {
                #pragma unroll
                for (int s = 0; s < 2; s++) {
                    #pragma unroll
                    for (int b = 0; b < BT; b++) {
                        ulonglong2 hv = *(const ulonglong2*)&stg[s * BT * IN + b * IN + ki0 + kk * 4];
                        ffma2(acc[s][b], hv.x, wih[2*kk]);
                        ffma2(acc[s][b], hv.y, wih[2*kk+1]);
                    }
                }
            }
            #pragma unroll
            for (int s = 0; s < 2; s++)
                #pragma unroll
                for (int b = 0; b < BT; b++)
                    partials[s * 4096 + w * 512 + b * 32 + lane] = red2(acc[s][b]);
            __syncthreads();
            #pragma unroll
            for (int s = 0; s < 2; s++) {
                float* xpo = g_xp + (size_t)(t + s) * NB * HID;
                for (int r = tid; r < 512; r += NTH) {
                    float v = 0.f;
                    #pragma unroll
                    for (int ww = 0; ww < 8; ww++) v += partials[s * 4096 + ww * 512 + r];
                    xpo[(size_t)(b0 + (r >> 5)) * HID + j0 + (r & 31)] = v;
                }
            }
            // no trailing sync: stage is double-buffered, and the next iteration's
            // post-staging sync orders these partials reads before its writes
        }
    }
    // group barrier: covers hs[0] zeros (xp is self-produced/self-consumed)
    sw_barrier(&g_cnt[bt], &g_gen[bt], GCTA);

    // ---------------- scan: h_{t+1} = tanh(xp + h W_hh^T + b) -----------------
    {
        const int kw0 = w * KW;
        unsigned long long whh[KW / 2];   // 128 regs of register-resident W_hh
        {
            const ulonglong2* wrow = (const ulonglong2*)(w_hh + (size_t)j * HID + kw0);
            #pragma unroll
            for (int i = 0; i < KW / 4; i++) { ulonglong2 v = wrow[i]; whh[2*i] = v.x; whh[2*i+1] = v.y; }
        }
        const int   rb1   = tid >> 5;          // batch idx (within tile) of first owned output
        const int   rj    = tid & 31;
        const float biasv = bias[j0 + rj];

        // Flag-barrier base: flags are uniform at every launch boundary (each flag
        // gets exactly +SEQ per launch; 0 at load), so reading our OWN flag gives
        // a grid-consistent epoch base. Wraparound-safe via signed diff compares.
        unsigned fbase;
        asm volatile("ld.relaxed.gpu.global.u32 %0, [%1];" : "=r"(fbase) : "l"(&g_flag[bt][jt]));

        // loop-invariant pointers for the epilogue (hoisted off the critical path)
        const float* xp_base = g_xp + (size_t)(b0 + rb1) * HID + j0 + rj;      // + t*NB*HID
        float*       hw_base = hs + (size_t)(b0 + rb1) * HID + j0 + rj;        // + (t+1)*NB*HID

        for (int t = 0; t < SEQ; t++) {
            // prefetch this step's xp values (immutable; latency hidden by FMA loop)
            const float* xp = xp_base + (size_t)t * NB * HID;
            float xpre0 = __ldg(xp);
            float xpre1 = __ldg(xp + (size_t)8 * HID);

            // stage h_t rows b0..b0+15 (contiguous) into SMEM
            const float* hsrc = hs + (size_t)t * NB * HID + (size_t)b0 * HID;
            for (int idx = tid; idx < BT * HID / 4; idx += NTH)
                ((float4*)stage)[idx] = ((const float4*)hsrc)[idx];
            __syncthreads();

            #pragma unroll 1
            for (int half = 0; half < 2; half++) {     // 2 x 8 batches (reg pressure)
                unsigned long long acc[8];
                #pragma unroll
                for (int b = 0; b < 8; b++) acc[b] = 0ull;
                const float* sb = stage + (half * 8) * HID + kw0;
                #pragma unroll
                for (int kk = 0; kk < KW / 4; kk++) {
                    #pragma unroll
                    for (int b = 0; b < 8; b++) {
                        ulonglong2 hv = *(const ulonglong2*)&sb[b * HID + kk * 4];
                        ffma2(acc[b], hv.x, whh[2*kk]);
                        ffma2(acc[b], hv.y, whh[2*kk+1]);
                    }
                }
                #pragma unroll
                for (int b = 0; b < 8; b++)
                    partials[w * 512 + (half * 8 + b) * 32 + lane] = red2(acc[b]);
            }
            __syncthreads();

            {
                float* hdst = hw_base + (size_t)(t + 1) * NB * HID;
                #pragma unroll
                for (int u = 0; u < 2; u++) {
                    int r = tid + u * NTH;
                    float s = 0.f;
                    #pragma unroll
                    for (int ww = 0; ww < 8; ww++) s += partials[ww * 512 + r];
                    s += (u ? xpre1 : xpre0) + biasv;
                    hdst[(size_t)(u * 8) * HID] = tanhf(s);
                }
            }

            // ---- flag-vector group barrier (parallel arrive, coalesced poll) ----
            // CTA-wide h-stores above are ordered into thread0's gpu-scope release
            // by this __syncthreads (CG grid.sync causality pattern).
            __syncthreads();
            const unsigned target = fbase + (unsigned)(t + 1);
            if (w == 0) {
                if (lane == 0) {
                    asm volatile("st.release.gpu.global.u32 [%0], %1;"
                                 :: "l"(&g_flag[bt][jt]), "r"(target));
                }
                unsigned v;
                do {
                    asm volatile("ld.relaxed.gpu.global.u32 %0, [%1];"
                                 : "=r"(v) : "l"(&g_flag[bt][lane]));
                } while (__any_sync(0xffffffffu, (int)(v - target) < 0));
                asm volatile("fence.acq_rel.gpu;" ::: "memory");
            }
            __syncthreads();
        }
    }

    // full-grid barrier before fc (fc reads h rows across all groups)
    sw_barrier(&g_cnt_all, &g_gen_all, GRID);

    // ---------------- fc: out = h_S @ fc_w^T + fc_b ---------------------------
    {
        const float* hlast = hs + (size_t)SEQ * NB * HID;
        int gtid = blockIdx.x * NTH + tid;
        if (gtid < NB * ONN) {
            int b = gtid >> 8;
            int o = gtid & 255;
            const float4* hp = (const float4*)(hlast + (size_t)b * HID);
            const float4* wp = (const float4*)(fc_w + (size_t)o * HID);
            float s = fc_b[o];
            #pragma unroll 16
            for (int k = 0; k < HID / 4; k++) {
                float4 hv = hp[k], wv = wp[k];
                s += hv.x * wv.x + hv.y * wv.y + hv.z * wv.z + hv.w * wv.w;
            }
            out[gtid] = s;
        }
    }
}

extern "C" void kernel_launch(void* const* d_in, const int* in_sizes, int n_in,
                              void* d_out, int out_size) {
    const float* x    = (const float*)d_in[0];
    const float* w_ih = (const float*)d_in[1];
    const float* w_hh = (const float*)d_in[2];
    const float* bias = (const float*)d_in[3];
    const float* fc_w = (const float*)d_in[4];
    const float* fc_b = (const float*)d_in[5];
    float* out = (float*)d_out;

    int smem_bytes = (BT * HID + 2 * 8 * 512) * sizeof(float);  // 96 KB
    cudaFuncSetAttribute(rnn_kernel, cudaFuncAttributeMaxDynamicSharedMemorySize, smem_bytes);
    rnn_kernel<<<GRID, NTH, smem_bytes>>>(x, w_ih, w_hh, bias, fc_w, fc_b, out);
}